// round 11
// baseline (speedup 1.0000x reference)
#include <cuda_runtime.h>
#include <cuda_bf16.h>
#include <math.h>

// ---------------------------------------------------------------------------
// CrossTransformerBlock3D: 32x32x32 voxels, DIM=192, 12 heads x 16, WS=(2,2,2)
// GEMMs: tf32 mma.m16n8k8, 128x96 block tile, cp.async double-buffered.
// Attention: 4 w-adjacent windows per CTA (384 thr), shared slab staging
// (54 slabs/CTA vs 104), bf16 kv, f32x2 FMA, triple-buffered, 1 sync/slab.
// ---------------------------------------------------------------------------

#define TOKENS 32768
#define DIM 192
#define HID 384
#define HEADS 12
#define HD 16

__device__ float g_xn  [TOKENS * DIM];
__device__ float g_xan [TOKENS * DIM];
__device__ float g_q   [TOKENS * DIM];
__device__ __nv_bfloat16 g_kv[TOKENS * HID];
__device__ float g_attn[TOKENS * DIM];
__device__ float g_x1  [TOKENS * DIM];
__device__ float g_x1n [TOKENS * DIM];
__device__ float g_h   [TOKENS * HID];

typedef unsigned long long u64;
__device__ __forceinline__ u64 fma2(u64 a, u64 b, u64 c)
{
    u64 d; asm("fma.rn.f32x2 %0,%1,%2,%3;" : "=l"(d) : "l"(a), "l"(b), "l"(c)); return d;
}
__device__ __forceinline__ u64 pack2(float lo, float hi)
{
    u64 d; asm("mov.b64 %0,{%1,%2};" : "=l"(d) : "f"(lo), "f"(hi)); return d;
}
__device__ __forceinline__ float2 unpack2(u64 v)
{
    float lo, hi; asm("mov.b64 {%0,%1},%2;" : "=f"(lo), "=f"(hi) : "l"(v));
    return make_float2(lo, hi);
}

// --------------------------- LayerNorm (warp per row, C=192) ----------------
__global__ void ln_kernel(const float* __restrict__ x, const float* __restrict__ g,
                          const float* __restrict__ b, float* __restrict__ o, int rows)
{
    int warp = (blockIdx.x * blockDim.x + threadIdx.x) >> 5;
    int lane = threadIdx.x & 31;
    if (warp >= rows) return;
    const float* xr = x + (size_t)warp * DIM;
    float v[6];
    float s = 0.f, s2 = 0.f;
#pragma unroll
    for (int i = 0; i < 6; i++) {
        v[i] = xr[lane + i * 32];
        s += v[i];
        s2 += v[i] * v[i];
    }
#pragma unroll
    for (int off = 16; off; off >>= 1) {
        s  += __shfl_xor_sync(0xffffffffu, s,  off);
        s2 += __shfl_xor_sync(0xffffffffu, s2, off);
    }
    float mean = s * (1.f / DIM);
    float var  = s2 * (1.f / DIM) - mean * mean;
    float rstd = rsqrtf(var + 1e-5f);
    float* orow = o + (size_t)warp * DIM;
#pragma unroll
    for (int i = 0; i < 6; i++) {
        int c = lane + i * 32;
        orow[c] = (v[i] - mean) * rstd * g[c] + b[c];
    }
}

// --------------------------- cp.async helpers -------------------------------
__device__ __forceinline__ void cp16(void* dst_smem, const void* src)
{
    unsigned d = (unsigned)__cvta_generic_to_shared(dst_smem);
    asm volatile("cp.async.ca.shared.global [%0], [%1], 16;" :: "r"(d), "l"(src));
}
#define CP_COMMIT asm volatile("cp.async.commit_group;")
#define CP_WAIT0  asm volatile("cp.async.wait_group 0;")

// --------------------------- tf32 tensor-core GEMM --------------------------
#define MMA_TF32(d, a, b)                                                     \
    asm volatile("mma.sync.aligned.m16n8k8.row.col.f32.tf32.tf32.f32 "        \
                 "{%0,%1,%2,%3}, {%4,%5,%6,%7}, {%8,%9}, {%0,%1,%2,%3};"      \
                 : "+f"(d[0]), "+f"(d[1]), "+f"(d[2]), "+f"(d[3])             \
                 : "r"(a[0]), "r"(a[1]), "r"(a[2]), "r"(a[3]),                \
                   "r"(b[0]), "r"(b[1]))

template <bool RES, bool GELU, bool OB>
__global__ __launch_bounds__(128, 3) void gemm_tc(const float* __restrict__ A,
                                                  const float* __restrict__ B,
                                                  const float* __restrict__ bias,
                                                  const float* __restrict__ resid,
                                                  void* __restrict__ Cv,
                                                  int M, int N, int K)
{
    __shared__ __align__(16) float As[2][128][20];
    __shared__ __align__(16) float Bs[2][16][104];

    const int tid = threadIdx.x;
    const int bm = blockIdx.y * 128;
    const int bn = blockIdx.x * 96;
    const int lane = tid & 31, w = tid >> 5;
    const int g = lane >> 2, tg = lane & 3;
    const int wr = (w & 1) * 64;
    const int wc = (w >> 1) * 48;

    float acc[4][6][4];
#pragma unroll
    for (int mi = 0; mi < 4; mi++)
#pragma unroll
        for (int ni = 0; ni < 6; ni++)
#pragma unroll
            for (int r = 0; r < 4; r++) acc[mi][ni][r] = 0.f;

    const int nchunks = K >> 4;

    {
#pragma unroll
        for (int i = 0; i < 4; i++) {
            int f = tid + i * 128;
            int r = f >> 2, c4 = (f & 3) * 4;
            cp16(&As[0][r][c4], &A[(size_t)(bm + r) * K + c4]);
        }
#pragma unroll
        for (int i = 0; i < 3; i++) {
            int f = tid + i * 128;
            int kr = f / 24, nq = (f % 24) * 4;
            cp16(&Bs[0][kr][nq], &B[(size_t)kr * N + bn + nq]);
        }
        CP_COMMIT;
    }

    int s = 0;
    for (int ci = 0; ci < nchunks; ci++, s ^= 1) {
        CP_WAIT0;
        __syncthreads();

        if (ci + 1 < nchunks) {
            int k0 = (ci + 1) << 4;
#pragma unroll
            for (int i = 0; i < 4; i++) {
                int f = tid + i * 128;
                int r = f >> 2, c4 = (f & 3) * 4;
                cp16(&As[s ^ 1][r][c4], &A[(size_t)(bm + r) * K + k0 + c4]);
            }
#pragma unroll
            for (int i = 0; i < 3; i++) {
                int f = tid + i * 128;
                int kr = f / 24, nq = (f % 24) * 4;
                cp16(&Bs[s ^ 1][kr][nq], &B[(size_t)(k0 + kr) * N + bn + nq]);
            }
            CP_COMMIT;
        }

#pragma unroll
        for (int kk = 0; kk < 2; kk++) {
            unsigned a[4][4], b[6][2];
#pragma unroll
            for (int mi = 0; mi < 4; mi++) {
                int r = wr + mi * 16 + g;
                a[mi][0] = __float_as_uint(As[s][r    ][kk * 8 + tg]);
                a[mi][1] = __float_as_uint(As[s][r + 8][kk * 8 + tg]);
                a[mi][2] = __float_as_uint(As[s][r    ][kk * 8 + tg + 4]);
                a[mi][3] = __float_as_uint(As[s][r + 8][kk * 8 + tg + 4]);
            }
#pragma unroll
            for (int ni = 0; ni < 6; ni++) {
                int n = wc + ni * 8 + g;
                b[ni][0] = __float_as_uint(Bs[s][kk * 8 + tg    ][n]);
                b[ni][1] = __float_as_uint(Bs[s][kk * 8 + tg + 4][n]);
            }
#pragma unroll
            for (int mi = 0; mi < 4; mi++)
#pragma unroll
                for (int ni = 0; ni < 6; ni++)
                    MMA_TF32(acc[mi][ni], a[mi], b[ni]);
        }
        __syncthreads();
    }

    float* Cf = (float*)Cv;
    __nv_bfloat16* Cb = (__nv_bfloat16*)Cv;
#pragma unroll
    for (int mi = 0; mi < 4; mi++) {
#pragma unroll
        for (int ni = 0; ni < 6; ni++) {
            int col = bn + wc + ni * 8 + tg * 2;
            float b0 = bias[col], b1 = bias[col + 1];
#pragma unroll
            for (int half = 0; half < 2; half++) {
                int row = bm + wr + mi * 16 + g + half * 8;
                float v0 = acc[mi][ni][half * 2 + 0] + b0;
                float v1 = acc[mi][ni][half * 2 + 1] + b1;
                if (GELU) {
                    v0 = 0.5f * v0 * (1.f + erff(v0 * 0.70710678118654752f));
                    v1 = 0.5f * v1 * (1.f + erff(v1 * 0.70710678118654752f));
                }
                if (RES) {
                    v0 += resid[(size_t)row * N + col];
                    v1 += resid[(size_t)row * N + col + 1];
                }
                if (OB) {
                    *(__nv_bfloat162*)&Cb[(size_t)row * N + col] = __floats2bfloat162_rn(v0, v1);
                } else {
                    *(float2*)&Cf[(size_t)row * N + col] = make_float2(v0, v1);
                }
            }
        }
    }
}

// --------------------------- windowed cross attention -----------------------
// CTA = 4 w-adjacent windows (wd, wh, ww0..ww0+3). 384 threads = 4 x 96,
// thread -> window j = tid/96, (head, query) within. Union slab set
// (3x3x6 = up to 54) staged once per CTA; window j participates when the
// slab's w-offset relative to wwj is in {-1,0,1} and it is not that
// window's slab-20 (offset (+1,-1,+1), always padded in the reference).
// Sum-only softmax with fixed shift m = s_pad.
__global__ __launch_bounds__(384, 2) void attn_kernel(const float* __restrict__ q,
                                                      const __nv_bfloat16* __restrict__ kv,
                                                      const float* __restrict__ bkv,
                                                      float* __restrict__ out)
{
    __shared__ float kv_sh[3][8 * HID];       // 36 KB
    __shared__ int sh_vlist[55];
    __shared__ int sh_nv;

    const int bid = blockIdx.x;               // 16*16*4 = 1024
    const int wg = bid & 3;
    const int wh = (bid >> 2) & 15;
    const int wd = bid >> 6;
    const int ww0 = wg * 4;
    const int tid = threadIdx.x;

    // thread 0 enumerates the CTA's valid slab list (in-range only)
    if (tid == 0) {
        int nv = 0;
#pragma unroll
        for (int dd = -1; dd <= 1; dd++) {
            int nd = wd + dd;
            if ((unsigned)nd >= 16u) continue;
#pragma unroll
            for (int dh = -1; dh <= 1; dh++) {
                int nh = wh + dh;
                if ((unsigned)nh >= 16u) continue;
#pragma unroll
                for (int wi = 0; wi < 6; wi++) {
                    int nw = ww0 - 1 + wi;
                    if ((unsigned)nw >= 16u) continue;
                    sh_vlist[nv++] = (dd + 1) << 10 | (dh + 1) << 5 | nw;
                }
            }
        }
        sh_nv = nv;
    }

    const int j = tid / 96;                   // window within CTA
    const int wtid = tid % 96;
    const int h = wtid >> 3, qi = wtid & 7;
    const int wwj = ww0 + j;

    // per-window pad count (27 slots; slot-20 + out-of-range are padded)
    int npad = 0;
#pragma unroll
    for (int sl = 0; sl < 27; sl++) {
        int nd = wd + sl / 9 - 1;
        int nh = wh + (sl / 3) % 3 - 1;
        int nw = wwj + sl % 3 - 1;
        bool valid = (sl != 20) && (unsigned)nd < 16u && (unsigned)nh < 16u && (unsigned)nw < 16u;
        if (!valid) npad++;
    }

    // q into registers, packed f32x2
    u64 qp[8], av[8];
    float l = 0.f, s_pad = 0.f;
    const int voxq = ((wd * 2 + (qi >> 2)) * 32 + wh * 2 + ((qi >> 1) & 1)) * 32 + wwj * 2 + (qi & 1);
    {
        const float2* q2 = (const float2*)&q[(size_t)voxq * DIM + h * HD];
        const float2* bk2 = (const float2*)&bkv[h * HD];
#pragma unroll
        for (int p = 0; p < 8; p++) {
            float2 t2 = q2[p];
            float2 bk = bk2[p];
            t2.x *= 0.25f; t2.y *= 0.25f;
            s_pad += t2.x * bk.x + t2.y * bk.y;
            qp[p] = pack2(t2.x, t2.y);
            av[p] = pack2(0.f, 0.f);
        }
    }

    // staging lane: one 16B chunk (8 bf16) per thread per slab
    const int st_t = tid / 48;                // token 0..7
    const int st_c8 = tid % 48;               // 8-elem chunk 0..47

    __syncthreads();                          // publish sh_vlist / sh_nv
    const int nv = sh_nv;

    // preload slab 0
    uint4 stg;
    {
        int e = sh_vlist[0];
        int nd = wd + (e >> 10) - 1, nh = wh + ((e >> 5) & 15) - 1, nw = e & 31;
        int vox = ((nd * 2 + (st_t >> 2)) * 32 + nh * 2 + ((st_t >> 1) & 1)) * 32 + nw * 2 + (st_t & 1);
        stg = *(const uint4*)&kv[(size_t)vox * HID + st_c8 * 8];
        const __nv_bfloat162* hb = (const __nv_bfloat162*)&stg;
        float* dst = &kv_sh[0][st_t * HID + st_c8 * 8];
        float2 f0 = __bfloat1622float2(hb[0]);
        float2 f1 = __bfloat1622float2(hb[1]);
        float2 f2 = __bfloat1622float2(hb[2]);
        float2 f3 = __bfloat1622float2(hb[3]);
        *(float4*)dst       = make_float4(f0.x, f0.y, f1.x, f1.y);
        *(float4*)(dst + 4) = make_float4(f2.x, f2.y, f3.x, f3.y);
    }
    __syncthreads();

    for (int i = 0; i < nv; i++) {
        const int rbuf = i % 3, wbuf = (i + 1) % 3;
        const int e = sh_vlist[i];
        const int dd = (e >> 10) - 1, dh = ((e >> 5) & 15) - 1, nw = e & 31;
        const int dnw = nw - wwj;

        // prefetch next slab to registers
        if (i + 1 < nv) {
            int e2 = sh_vlist[i + 1];
            int nd2 = wd + (e2 >> 10) - 1, nh2 = wh + ((e2 >> 5) & 15) - 1, nw2 = e2 & 31;
            int vox = ((nd2 * 2 + (st_t >> 2)) * 32 + nh2 * 2 + ((st_t >> 1) & 1)) * 32 + nw2 * 2 + (st_t & 1);
            stg = *(const uint4*)&kv[(size_t)vox * HID + st_c8 * 8];
        }

        const bool part = (dnw >= -1) && (dnw <= 1) && !(dd == 1 && dh == -1 && dnw == 1);
        if (part) {
#pragma unroll
            for (int t = 0; t < 8; t++) {
                const u64* kp = (const u64*)&kv_sh[rbuf][t * HID + h * HD];
                u64 s2a = pack2(0.f, 0.f), s2b = pack2(0.f, 0.f);
#pragma unroll
                for (int p = 0; p < 4; p++) {
                    s2a = fma2(qp[2 * p    ], kp[2 * p    ], s2a);
                    s2b = fma2(qp[2 * p + 1], kp[2 * p + 1], s2b);
                }
                float2 sa = unpack2(s2a), sb = unpack2(s2b);
                float pw = __expf(sa.x + sa.y + sb.x + sb.y - s_pad);
                l += pw;
                u64 p2 = pack2(pw, pw);
                const u64* vp = (const u64*)&kv_sh[rbuf][t * HID + DIM + h * HD];
#pragma unroll
                for (int p = 0; p < 8; p++) av[p] = fma2(p2, vp[p], av[p]);
            }
        }

        // stage next slab into wbuf
        if (i + 1 < nv) {
            const __nv_bfloat162* hb = (const __nv_bfloat162*)&stg;
            float* dst = &kv_sh[wbuf][st_t * HID + st_c8 * 8];
            float2 f0 = __bfloat1622float2(hb[0]);
            float2 f1 = __bfloat1622float2(hb[1]);
            float2 f2 = __bfloat1622float2(hb[2]);
            float2 f3 = __bfloat1622float2(hb[3]);
            *(float4*)dst       = make_float4(f0.x, f0.y, f1.x, f1.y);
            *(float4*)(dst + 4) = make_float4(f2.x, f2.y, f3.x, f3.y);
        }
        __syncthreads();
    }

    {
        float pp = 8.f * (float)npad;     // exp(s_pad - s_pad) = 1 per padded key
        l += pp;
        const float2* bv2 = (const float2*)&bkv[DIM + h * HD];
        float inv = 1.f / l;
        float* orow = &out[(size_t)voxq * DIM + h * HD];
#pragma unroll
        for (int p = 0; p < 8; p++) {
            float2 a2 = unpack2(av[p]);
            float2 bv = bv2[p];
            *(float2*)&orow[p * 2] = make_float2((a2.x + pp * bv.x) * inv,
                                                 (a2.y + pp * bv.y) * inv);
        }
    }
}

// ---------------------------------------------------------------------------
extern "C" void kernel_launch(void* const* d_in, const int* in_sizes, int n_in,
                              void* d_out, int out_size)
{
    const float* x       = (const float*)d_in[0];
    const float* xa      = (const float*)d_in[1];
    const float* norm1_g = (const float*)d_in[2];
    const float* norm1_b = (const float*)d_in[3];
    const float* norm2_g = (const float*)d_in[4];
    const float* norm2_b = (const float*)d_in[5];
    const float* Wq      = (const float*)d_in[6];
    const float* bq      = (const float*)d_in[7];
    const float* Wkv     = (const float*)d_in[8];
    const float* bkv     = (const float*)d_in[9];
    const float* Wp      = (const float*)d_in[10];
    const float* bp      = (const float*)d_in[11];
    const float* W1      = (const float*)d_in[12];
    const float* b1      = (const float*)d_in[13];
    const float* W2      = (const float*)d_in[14];
    const float* b2      = (const float*)d_in[15];
    float* out = (float*)d_out;

    float* xn = nullptr; float* xan = nullptr; float* qb = nullptr;
    __nv_bfloat16* kvb = nullptr;
    float* attn = nullptr; float* x1 = nullptr; float* x1n = nullptr; float* hb = nullptr;
    cudaGetSymbolAddress((void**)&xn,   g_xn);
    cudaGetSymbolAddress((void**)&xan,  g_xan);
    cudaGetSymbolAddress((void**)&qb,   g_q);
    cudaGetSymbolAddress((void**)&kvb,  g_kv);
    cudaGetSymbolAddress((void**)&attn, g_attn);
    cudaGetSymbolAddress((void**)&x1,   g_x1);
    cudaGetSymbolAddress((void**)&x1n,  g_x1n);
    cudaGetSymbolAddress((void**)&hb,   g_h);

    const int ln_blocks = TOKENS / 8;

    ln_kernel<<<ln_blocks, 256>>>(x,  norm1_g, norm1_b, xn,  TOKENS);
    ln_kernel<<<ln_blocks, 256>>>(xa, norm1_g, norm1_b, xan, TOKENS);

    gemm_tc<false, false, false><<<dim3(DIM / 96, TOKENS / 128), 128>>>(xn,  Wq,  bq,  nullptr, qb,  TOKENS, DIM, DIM);
    gemm_tc<false, false, true ><<<dim3(HID / 96, TOKENS / 128), 128>>>(xan, Wkv, bkv, nullptr, kvb, TOKENS, HID, DIM);

    attn_kernel<<<1024, 384>>>(qb, kvb, bkv, attn);

    gemm_tc<true, false, false><<<dim3(DIM / 96, TOKENS / 128), 128>>>(attn, Wp, bp, x, x1, TOKENS, DIM, DIM);

    ln_kernel<<<ln_blocks, 256>>>(x1, norm2_g, norm2_b, x1n, TOKENS);

    gemm_tc<false, true, false><<<dim3(HID / 96, TOKENS / 128), 128>>>(x1n, W1, b1, nullptr, hb, TOKENS, HID, DIM);
    gemm_tc<true, false, false><<<dim3(DIM / 96, TOKENS / 128), 128>>>(hb, W2, b2, x1, out, TOKENS, DIM, HID);
}

// round 14
// speedup vs baseline: 1.1733x; 1.1733x over previous
#include <cuda_runtime.h>
#include <cuda_bf16.h>
#include <math.h>

// ---------------------------------------------------------------------------
// CrossTransformerBlock3D: 32x32x32 voxels, DIM=192, 12 heads x 16, WS=(2,2,2)
// GEMMs: tf32 mma.m16n8k8, 128x96 block tile, cp.async double-buffered.
// Attention: 1 window/CTA, 192 threads = (12 heads x 8 queries x 2 key-halves),
// bf16 kv, float4 smem loads, f32x2 FMA, triple-buffered, 1 sync/slab,
// shfl-pair reduction across key halves. Fixed-shift sum-only softmax.
// ---------------------------------------------------------------------------

#define TOKENS 32768
#define DIM 192
#define HID 384
#define HEADS 12
#define HD 16
#define KSTRIDE (HID + 4)          // padded smem row stride (floats)

__device__ float g_xn  [TOKENS * DIM];
__device__ float g_xan [TOKENS * DIM];
__device__ float g_q   [TOKENS * DIM];
__device__ __nv_bfloat16 g_kv[TOKENS * HID];
__device__ float g_attn[TOKENS * DIM];
__device__ float g_x1  [TOKENS * DIM];
__device__ float g_x1n [TOKENS * DIM];
__device__ float g_h   [TOKENS * HID];

typedef unsigned long long u64;
__device__ __forceinline__ u64 fma2(u64 a, u64 b, u64 c)
{
    u64 d; asm("fma.rn.f32x2 %0,%1,%2,%3;" : "=l"(d) : "l"(a), "l"(b), "l"(c)); return d;
}
__device__ __forceinline__ u64 pack2(float lo, float hi)
{
    u64 d; asm("mov.b64 %0,{%1,%2};" : "=l"(d) : "f"(lo), "f"(hi)); return d;
}
__device__ __forceinline__ float2 unpack2(u64 v)
{
    float lo, hi; asm("mov.b64 {%0,%1},%2;" : "=f"(lo), "=f"(hi) : "l"(v));
    return make_float2(lo, hi);
}

// --------------------------- LayerNorm (warp per row, C=192) ----------------
__global__ void ln_kernel(const float* __restrict__ x, const float* __restrict__ g,
                          const float* __restrict__ b, float* __restrict__ o, int rows)
{
    int warp = (blockIdx.x * blockDim.x + threadIdx.x) >> 5;
    int lane = threadIdx.x & 31;
    if (warp >= rows) return;
    const float* xr = x + (size_t)warp * DIM;
    float v[6];
    float s = 0.f, s2 = 0.f;
#pragma unroll
    for (int i = 0; i < 6; i++) {
        v[i] = xr[lane + i * 32];
        s += v[i];
        s2 += v[i] * v[i];
    }
#pragma unroll
    for (int off = 16; off; off >>= 1) {
        s  += __shfl_xor_sync(0xffffffffu, s,  off);
        s2 += __shfl_xor_sync(0xffffffffu, s2, off);
    }
    float mean = s * (1.f / DIM);
    float var  = s2 * (1.f / DIM) - mean * mean;
    float rstd = rsqrtf(var + 1e-5f);
    float* orow = o + (size_t)warp * DIM;
#pragma unroll
    for (int i = 0; i < 6; i++) {
        int c = lane + i * 32;
        orow[c] = (v[i] - mean) * rstd * g[c] + b[c];
    }
}

// --------------------------- cp.async helpers -------------------------------
__device__ __forceinline__ void cp16(void* dst_smem, const void* src)
{
    unsigned d = (unsigned)__cvta_generic_to_shared(dst_smem);
    asm volatile("cp.async.ca.shared.global [%0], [%1], 16;" :: "r"(d), "l"(src));
}
#define CP_COMMIT asm volatile("cp.async.commit_group;")
#define CP_WAIT0  asm volatile("cp.async.wait_group 0;")

// --------------------------- tf32 tensor-core GEMM --------------------------
#define MMA_TF32(d, a, b)                                                     \
    asm volatile("mma.sync.aligned.m16n8k8.row.col.f32.tf32.tf32.f32 "        \
                 "{%0,%1,%2,%3}, {%4,%5,%6,%7}, {%8,%9}, {%0,%1,%2,%3};"      \
                 : "+f"(d[0]), "+f"(d[1]), "+f"(d[2]), "+f"(d[3])             \
                 : "r"(a[0]), "r"(a[1]), "r"(a[2]), "r"(a[3]),                \
                   "r"(b[0]), "r"(b[1]))

template <bool RES, bool GELU, bool OB>
__global__ __launch_bounds__(128, 3) void gemm_tc(const float* __restrict__ A,
                                                  const float* __restrict__ B,
                                                  const float* __restrict__ bias,
                                                  const float* __restrict__ resid,
                                                  void* __restrict__ Cv,
                                                  int M, int N, int K)
{
    __shared__ __align__(16) float As[2][128][20];
    __shared__ __align__(16) float Bs[2][16][104];

    const int tid = threadIdx.x;
    const int bm = blockIdx.y * 128;
    const int bn = blockIdx.x * 96;
    const int lane = tid & 31, w = tid >> 5;
    const int g = lane >> 2, tg = lane & 3;
    const int wr = (w & 1) * 64;
    const int wc = (w >> 1) * 48;

    float acc[4][6][4];
#pragma unroll
    for (int mi = 0; mi < 4; mi++)
#pragma unroll
        for (int ni = 0; ni < 6; ni++)
#pragma unroll
            for (int r = 0; r < 4; r++) acc[mi][ni][r] = 0.f;

    const int nchunks = K >> 4;

    {
#pragma unroll
        for (int i = 0; i < 4; i++) {
            int f = tid + i * 128;
            int r = f >> 2, c4 = (f & 3) * 4;
            cp16(&As[0][r][c4], &A[(size_t)(bm + r) * K + c4]);
        }
#pragma unroll
        for (int i = 0; i < 3; i++) {
            int f = tid + i * 128;
            int kr = f / 24, nq = (f % 24) * 4;
            cp16(&Bs[0][kr][nq], &B[(size_t)kr * N + bn + nq]);
        }
        CP_COMMIT;
    }

    int s = 0;
    for (int ci = 0; ci < nchunks; ci++, s ^= 1) {
        CP_WAIT0;
        __syncthreads();

        if (ci + 1 < nchunks) {
            int k0 = (ci + 1) << 4;
#pragma unroll
            for (int i = 0; i < 4; i++) {
                int f = tid + i * 128;
                int r = f >> 2, c4 = (f & 3) * 4;
                cp16(&As[s ^ 1][r][c4], &A[(size_t)(bm + r) * K + k0 + c4]);
            }
#pragma unroll
            for (int i = 0; i < 3; i++) {
                int f = tid + i * 128;
                int kr = f / 24, nq = (f % 24) * 4;
                cp16(&Bs[s ^ 1][kr][nq], &B[(size_t)(k0 + kr) * N + bn + nq]);
            }
            CP_COMMIT;
        }

#pragma unroll
        for (int kk = 0; kk < 2; kk++) {
            unsigned a[4][4], b[6][2];
#pragma unroll
            for (int mi = 0; mi < 4; mi++) {
                int r = wr + mi * 16 + g;
                a[mi][0] = __float_as_uint(As[s][r    ][kk * 8 + tg]);
                a[mi][1] = __float_as_uint(As[s][r + 8][kk * 8 + tg]);
                a[mi][2] = __float_as_uint(As[s][r    ][kk * 8 + tg + 4]);
                a[mi][3] = __float_as_uint(As[s][r + 8][kk * 8 + tg + 4]);
            }
#pragma unroll
            for (int ni = 0; ni < 6; ni++) {
                int n = wc + ni * 8 + g;
                b[ni][0] = __float_as_uint(Bs[s][kk * 8 + tg    ][n]);
                b[ni][1] = __float_as_uint(Bs[s][kk * 8 + tg + 4][n]);
            }
#pragma unroll
            for (int mi = 0; mi < 4; mi++)
#pragma unroll
                for (int ni = 0; ni < 6; ni++)
                    MMA_TF32(acc[mi][ni], a[mi], b[ni]);
        }
        __syncthreads();
    }

    float* Cf = (float*)Cv;
    __nv_bfloat16* Cb = (__nv_bfloat16*)Cv;
#pragma unroll
    for (int mi = 0; mi < 4; mi++) {
#pragma unroll
        for (int ni = 0; ni < 6; ni++) {
            int col = bn + wc + ni * 8 + tg * 2;
            float b0 = bias[col], b1 = bias[col + 1];
#pragma unroll
            for (int half = 0; half < 2; half++) {
                int row = bm + wr + mi * 16 + g + half * 8;
                float v0 = acc[mi][ni][half * 2 + 0] + b0;
                float v1 = acc[mi][ni][half * 2 + 1] + b1;
                if (GELU) {
                    v0 = 0.5f * v0 * (1.f + erff(v0 * 0.70710678118654752f));
                    v1 = 0.5f * v1 * (1.f + erff(v1 * 0.70710678118654752f));
                }
                if (RES) {
                    v0 += resid[(size_t)row * N + col];
                    v1 += resid[(size_t)row * N + col + 1];
                }
                if (OB) {
                    *(__nv_bfloat162*)&Cb[(size_t)row * N + col] = __floats2bfloat162_rn(v0, v1);
                } else {
                    *(float2*)&Cf[(size_t)row * N + col] = make_float2(v0, v1);
                }
            }
        }
    }
}

// --------------------------- windowed cross attention -----------------------
// Block = 1 window, 192 threads: tid = h*16 + qi*2 + half.
// half in {0,1} processes keys [4*half, 4*half+4) of each slab; partner
// (tid^1, same warp) merged at the end via shfl.xor. bf16 kv converted to
// fp32 at staging; float4 smem loads; triple buffer, 1 sync/slab.
// Fixed-shift sum-only softmax (m = s_pad).
__global__ __launch_bounds__(192) void attn_kernel(const float* __restrict__ q,
                                                   const __nv_bfloat16* __restrict__ kv,
                                                   const float* __restrict__ bkv,
                                                   float* __restrict__ out)
{
    __shared__ float kv_sh[3][8 * KSTRIDE];   // 3 x 8 x 388 floats = 36.4 KB
    __shared__ int sh_vlist[27];
    __shared__ int sh_nv;

    const int bid = blockIdx.x;
    const int wd = bid >> 8, wh = (bid >> 4) & 15, ww = bid & 15;
    const int tid = threadIdx.x;

    if (tid == 0) {
        int nv = 0;
#pragma unroll
        for (int sl = 0; sl < 27; sl++) {
            int nd = wd + sl / 9 - 1;
            int nh = wh + (sl / 3) % 3 - 1;
            int nw = ww + sl % 3 - 1;
            bool valid = (sl != 20) && (unsigned)nd < 16u && (unsigned)nh < 16u && (unsigned)nw < 16u;
            if (valid) sh_vlist[nv++] = (nd << 8) | (nh << 4) | nw;
        }
        sh_nv = nv;
    }

    const int h = tid >> 4;                 // 0..11
    const int qi = (tid >> 1) & 7;          // 0..7
    const int half = tid & 1;               // 0..1
    const int t0 = half * 4;                // first key this thread owns

    // q into registers, packed f32x2
    u64 qp[8], av[8];
    float l = 0.f, s_pad = 0.f;
    const int voxq = ((wd * 2 + (qi >> 2)) * 32 + wh * 2 + ((qi >> 1) & 1)) * 32 + ww * 2 + (qi & 1);
    {
        const float2* q2 = (const float2*)&q[(size_t)voxq * DIM + h * HD];
        const float2* bk2 = (const float2*)&bkv[h * HD];
#pragma unroll
        for (int p = 0; p < 8; p++) {
            float2 t2 = q2[p];
            float2 bk = bk2[p];
            t2.x *= 0.25f; t2.y *= 0.25f;
            s_pad += t2.x * bk.x + t2.y * bk.y;
            qp[p] = pack2(t2.x, t2.y);
            av[p] = pack2(0.f, 0.f);
        }
    }

    // staging: 384 16B-chunks (8 bf16 each), 2 per thread
    const int sa_t  = tid / 48,        sa_c = tid % 48;
    const int sb_t  = (tid + 192) / 48, sb_c = (tid + 192) % 48;

    __syncthreads();
    const int nv = sh_nv;
    const int npad = 27 - nv;

    uint4 stgA, stgB;
    // preload slab 0
    {
        int e = sh_vlist[0];
        int nd = e >> 8, nh = (e >> 4) & 15, nw = e & 15;
        int voxA = ((nd * 2 + (sa_t >> 2)) * 32 + nh * 2 + ((sa_t >> 1) & 1)) * 32 + nw * 2 + (sa_t & 1);
        int voxB = ((nd * 2 + (sb_t >> 2)) * 32 + nh * 2 + ((sb_t >> 1) & 1)) * 32 + nw * 2 + (sb_t & 1);
        stgA = *(const uint4*)&kv[(size_t)voxA * HID + sa_c * 8];
        stgB = *(const uint4*)&kv[(size_t)voxB * HID + sb_c * 8];
#pragma unroll
        for (int j = 0; j < 2; j++) {
            const uint4& sg = j ? stgB : stgA;
            int st = j ? sb_t : sa_t, sc = j ? sb_c : sa_c;
            const __nv_bfloat162* hb = (const __nv_bfloat162*)&sg;
            float* dst = &kv_sh[0][st * KSTRIDE + sc * 8];
            float2 f0 = __bfloat1622float2(hb[0]);
            float2 f1 = __bfloat1622float2(hb[1]);
            float2 f2 = __bfloat1622float2(hb[2]);
            float2 f3 = __bfloat1622float2(hb[3]);
            *(float4*)dst       = make_float4(f0.x, f0.y, f1.x, f1.y);
            *(float4*)(dst + 4) = make_float4(f2.x, f2.y, f3.x, f3.y);
        }
    }
    __syncthreads();

    for (int i = 0; i < nv; i++) {
        const int rbuf = i % 3, wbuf = (i + 1) % 3;

        if (i + 1 < nv) {
            int e = sh_vlist[i + 1];
            int nd = e >> 8, nh = (e >> 4) & 15, nw = e & 15;
            int voxA = ((nd * 2 + (sa_t >> 2)) * 32 + nh * 2 + ((sa_t >> 1) & 1)) * 32 + nw * 2 + (sa_t & 1);
            int voxB = ((nd * 2 + (sb_t >> 2)) * 32 + nh * 2 + ((sb_t >> 1) & 1)) * 32 + nw * 2 + (sb_t & 1);
            stgA = *(const uint4*)&kv[(size_t)voxA * HID + sa_c * 8];
            stgB = *(const uint4*)&kv[(size_t)voxB * HID + sb_c * 8];
        }

        // this thread's 4 keys
#pragma unroll
        for (int k = 0; k < 4; k++) {
            const int t = t0 + k;
            const float4* kp4 = (const float4*)&kv_sh[rbuf][t * KSTRIDE + h * HD];
            float4 k0 = kp4[0], k1 = kp4[1], k2 = kp4[2], k3 = kp4[3];
            u64 s2a = fma2(qp[0], pack2(k0.x, k0.y), pack2(0.f, 0.f));
            u64 s2b = fma2(qp[1], pack2(k0.z, k0.w), pack2(0.f, 0.f));
            s2a = fma2(qp[2], pack2(k1.x, k1.y), s2a);
            s2b = fma2(qp[3], pack2(k1.z, k1.w), s2b);
            s2a = fma2(qp[4], pack2(k2.x, k2.y), s2a);
            s2b = fma2(qp[5], pack2(k2.z, k2.w), s2b);
            s2a = fma2(qp[6], pack2(k3.x, k3.y), s2a);
            s2b = fma2(qp[7], pack2(k3.z, k3.w), s2b);
            float2 sa = unpack2(s2a), sb = unpack2(s2b);
            float pw = __expf(sa.x + sa.y + sb.x + sb.y - s_pad);
            l += pw;
            u64 p2 = pack2(pw, pw);
            const float4* vp4 = (const float4*)&kv_sh[rbuf][t * KSTRIDE + DIM + h * HD];
            float4 v0 = vp4[0], v1 = vp4[1], v2 = vp4[2], v3 = vp4[3];
            av[0] = fma2(p2, pack2(v0.x, v0.y), av[0]);
            av[1] = fma2(p2, pack2(v0.z, v0.w), av[1]);
            av[2] = fma2(p2, pack2(v1.x, v1.y), av[2]);
            av[3] = fma2(p2, pack2(v1.z, v1.w), av[3]);
            av[4] = fma2(p2, pack2(v2.x, v2.y), av[4]);
            av[5] = fma2(p2, pack2(v2.z, v2.w), av[5]);
            av[6] = fma2(p2, pack2(v3.x, v3.y), av[6]);
            av[7] = fma2(p2, pack2(v3.z, v3.w), av[7]);
        }

        if (i + 1 < nv) {
#pragma unroll
            for (int j = 0; j < 2; j++) {
                const uint4& sg = j ? stgB : stgA;
                int st = j ? sb_t : sa_t, sc = j ? sb_c : sa_c;
                const __nv_bfloat162* hb = (const __nv_bfloat162*)&sg;
                float* dst = &kv_sh[wbuf][st * KSTRIDE + sc * 8];
                float2 f0 = __bfloat1622float2(hb[0]);
                float2 f1 = __bfloat1622float2(hb[1]);
                float2 f2 = __bfloat1622float2(hb[2]);
                float2 f3 = __bfloat1622float2(hb[3]);
                *(float4*)dst       = make_float4(f0.x, f0.y, f1.x, f1.y);
                *(float4*)(dst + 4) = make_float4(f2.x, f2.y, f3.x, f3.y);
            }
        }
        __syncthreads();
    }

    // merge key-halves (partner = tid^1, same warp), add pad term, write
    {
        l += __shfl_xor_sync(0xffffffffu, l, 1);
        float pp = 8.f * (float)npad;
        l += pp;
        float inv = 1.f / l;
        const float2* bv2 = (const float2*)&bkv[DIM + h * HD];
        float* orow = &out[(size_t)voxq * DIM + h * HD];
#pragma unroll
        for (int p = 0; p < 8; p++) {
            float2 a2 = unpack2(av[p]);
            a2.x += __shfl_xor_sync(0xffffffffu, a2.x, 1);
            a2.y += __shfl_xor_sync(0xffffffffu, a2.y, 1);
            if ((p >> 2) == half) {
                float2 bv = bv2[p];
                *(float2*)&orow[p * 2] = make_float2((a2.x + pp * bv.x) * inv,
                                                     (a2.y + pp * bv.y) * inv);
            }
        }
    }
}

// ---------------------------------------------------------------------------
extern "C" void kernel_launch(void* const* d_in, const int* in_sizes, int n_in,
                              void* d_out, int out_size)
{
    const float* x       = (const float*)d_in[0];
    const float* xa      = (const float*)d_in[1];
    const float* norm1_g = (const float*)d_in[2];
    const float* norm1_b = (const float*)d_in[3];
    const float* norm2_g = (const float*)d_in[4];
    const float* norm2_b = (const float*)d_in[5];
    const float* Wq      = (const float*)d_in[6];
    const float* bq      = (const float*)d_in[7];
    const float* Wkv     = (const float*)d_in[8];
    const float* bkv     = (const float*)d_in[9];
    const float* Wp      = (const float*)d_in[10];
    const float* bp      = (const float*)d_in[11];
    const float* W1      = (const float*)d_in[12];
    const float* b1      = (const float*)d_in[13];
    const float* W2      = (const float*)d_in[14];
    const float* b2      = (const float*)d_in[15];
    float* out = (float*)d_out;

    float* xn = nullptr; float* xan = nullptr; float* qb = nullptr;
    __nv_bfloat16* kvb = nullptr;
    float* attn = nullptr; float* x1 = nullptr; float* x1n = nullptr; float* hb = nullptr;
    cudaGetSymbolAddress((void**)&xn,   g_xn);
    cudaGetSymbolAddress((void**)&xan,  g_xan);
    cudaGetSymbolAddress((void**)&qb,   g_q);
    cudaGetSymbolAddress((void**)&kvb,  g_kv);
    cudaGetSymbolAddress((void**)&attn, g_attn);
    cudaGetSymbolAddress((void**)&x1,   g_x1);
    cudaGetSymbolAddress((void**)&x1n,  g_x1n);
    cudaGetSymbolAddress((void**)&hb,   g_h);

    const int ln_blocks = TOKENS / 8;

    ln_kernel<<<ln_blocks, 256>>>(x,  norm1_g, norm1_b, xn,  TOKENS);
    ln_kernel<<<ln_blocks, 256>>>(xa, norm1_g, norm1_b, xan, TOKENS);

    gemm_tc<false, false, false><<<dim3(DIM / 96, TOKENS / 128), 128>>>(xn,  Wq,  bq,  nullptr, qb,  TOKENS, DIM, DIM);
    gemm_tc<false, false, true ><<<dim3(HID / 96, TOKENS / 128), 128>>>(xan, Wkv, bkv, nullptr, kvb, TOKENS, HID, DIM);

    attn_kernel<<<4096, 192>>>(qb, kvb, bkv, attn);

    gemm_tc<true, false, false><<<dim3(DIM / 96, TOKENS / 128), 128>>>(attn, Wp, bp, x, x1, TOKENS, DIM, DIM);

    ln_kernel<<<ln_blocks, 256>>>(x1, norm2_g, norm2_b, x1n, TOKENS);

    gemm_tc<false, true, false><<<dim3(HID / 96, TOKENS / 128), 128>>>(x1n, W1, b1, nullptr, hb, TOKENS, HID, DIM);
    gemm_tc<true, false, false><<<dim3(DIM / 96, TOKENS / 128), 128>>>(hb, W2, b2, x1, out, TOKENS, DIM, HID);
}